// round 1
// baseline (speedup 1.0000x reference)
#include <cuda_runtime.h>
#include <cstdint>

// Problem dims (fixed by the dataset)
#define BB   64
#define TT   1000
#define INN  512
#define HH   512
#define MM   (BB * TT)   // 64000

// Scratch: Wx intermediate [B*T, H] and diagonal-zeroed V
__device__ float g_Wx[MM * HH];        // 131 MB
__device__ float g_VZ[HH * HH];        // 1 MB

// ---------------------------------------------------------------------------
// Kernel 0: VZ = V with zero diagonal
// ---------------------------------------------------------------------------
__global__ void make_vz_kernel(const float* __restrict__ V) {
    int i = blockIdx.x * blockDim.x + threadIdx.x;
    if (i < HH * HH) {
        int r = i >> 9;
        int c = i & (HH - 1);
        g_VZ[i] = (r == c) ? 0.0f : V[i];
    }
}

// ---------------------------------------------------------------------------
// Kernel 1: SGEMM  C[m,n] = sum_k X[m,k] * W[n,k]   (NT, fp32)
//   M = 64000, N = 512, K = 512. Tiles 128x128x16, 256 threads, 8x8 microtile,
//   register double-buffered global loads.
// ---------------------------------------------------------------------------
#define BMT 128
#define BNT 128
#define BKT 16
#define SPAD 4

__global__ __launch_bounds__(256, 2) void sgemm_nt_kernel(
    const float* __restrict__ X, const float* __restrict__ W)
{
    __shared__ float As[BKT][BMT + SPAD];
    __shared__ float Bs[BKT][BNT + SPAD];

    const int tid = threadIdx.x;
    const int lr  = tid >> 2;          // 0..63
    const int lc  = (tid & 3) << 2;    // 0,4,8,12
    const int tx  = tid & 15;          // col group
    const int ty  = tid >> 4;          // row group

    const float* Xp = X + (size_t)blockIdx.x * BMT * INN;
    const float* Wp = W + (size_t)blockIdx.y * BNT * INN;

    float4 a0 = *(const float4*)(Xp + (size_t)lr * INN + lc);
    float4 a1 = *(const float4*)(Xp + (size_t)(lr + 64) * INN + lc);
    float4 b0 = *(const float4*)(Wp + (size_t)lr * INN + lc);
    float4 b1 = *(const float4*)(Wp + (size_t)(lr + 64) * INN + lc);

    float acc[8][8];
    #pragma unroll
    for (int i = 0; i < 8; i++)
        #pragma unroll
        for (int j = 0; j < 8; j++) acc[i][j] = 0.0f;

    int k0 = 0;
    for (;;) {
        __syncthreads();
        As[lc + 0][lr]      = a0.x; As[lc + 1][lr]      = a0.y;
        As[lc + 2][lr]      = a0.z; As[lc + 3][lr]      = a0.w;
        As[lc + 0][lr + 64] = a1.x; As[lc + 1][lr + 64] = a1.y;
        As[lc + 2][lr + 64] = a1.z; As[lc + 3][lr + 64] = a1.w;
        Bs[lc + 0][lr]      = b0.x; Bs[lc + 1][lr]      = b0.y;
        Bs[lc + 2][lr]      = b0.z; Bs[lc + 3][lr]      = b0.w;
        Bs[lc + 0][lr + 64] = b1.x; Bs[lc + 1][lr + 64] = b1.y;
        Bs[lc + 2][lr + 64] = b1.z; Bs[lc + 3][lr + 64] = b1.w;
        __syncthreads();

        k0 += BKT;
        const bool more = (k0 < INN);
        if (more) {
            a0 = *(const float4*)(Xp + (size_t)lr * INN + k0 + lc);
            a1 = *(const float4*)(Xp + (size_t)(lr + 64) * INN + k0 + lc);
            b0 = *(const float4*)(Wp + (size_t)lr * INN + k0 + lc);
            b1 = *(const float4*)(Wp + (size_t)(lr + 64) * INN + k0 + lc);
        }

        #pragma unroll
        for (int k = 0; k < BKT; k++) {
            float ra[8], rb[8];
            *(float4*)(ra)     = *(const float4*)(&As[k][ty * 8]);
            *(float4*)(ra + 4) = *(const float4*)(&As[k][ty * 8 + 4]);
            *(float4*)(rb)     = *(const float4*)(&Bs[k][tx * 8]);
            *(float4*)(rb + 4) = *(const float4*)(&Bs[k][tx * 8 + 4]);
            #pragma unroll
            for (int i = 0; i < 8; i++)
                #pragma unroll
                for (int j = 0; j < 8; j++)
                    acc[i][j] = fmaf(ra[i], rb[j], acc[i][j]);
        }
        if (!more) break;
    }

    float* Cp = g_Wx + (size_t)(blockIdx.x * BMT + ty * 8) * HH
                     + blockIdx.y * BNT + tx * 8;
    #pragma unroll
    for (int i = 0; i < 8; i++) {
        *(float4*)(Cp + (size_t)i * HH)     = make_float4(acc[i][0], acc[i][1], acc[i][2], acc[i][3]);
        *(float4*)(Cp + (size_t)i * HH + 4) = make_float4(acc[i][4], acc[i][5], acc[i][6], acc[i][7]);
    }
}

// ---------------------------------------------------------------------------
// Kernel 2: recurrent scan. One CTA per batch, 512 threads, thread h owns
// neuron h. ut lives in a register across all T steps. Binary spikes ->
// recurrent matvec is a sparse gather of VZ rows (list built per step via
// ballot + warp-prefix compaction). Step 0 uses continuous st0 -> dense.
// ---------------------------------------------------------------------------
__global__ __launch_bounds__(512, 1) void scan_kernel(
    const float* __restrict__ alpha,
    const float* __restrict__ ut0,
    const float* __restrict__ st0,
    float* __restrict__ out)
{
    const int b    = blockIdx.x;
    const int h    = threadIdx.x;
    const int lane = h & 31;
    const int wid  = h >> 5;

    __shared__ float s_v[HH];
    __shared__ int   s_list[HH];
    __shared__ int   s_wcnt[16];
    __shared__ int   s_woff[16];
    __shared__ int   s_total;

    const float a   = fminf(fmaxf(alpha[h], 0.81873075307798182f), 0.96078943915232320f);
    const float oma = 1.0f - a;

    float ut      = ut0[b * HH + h];
    float st_prev = st0[b * HH + h];   // continuous initial spike state

    s_v[h] = st_prev;
    __syncthreads();

    // Dense recurrent input for step 0: rec[h] = sum_j st0[j] * VZ[j][h]
    float rec;
    {
        float r0 = 0.f, r1 = 0.f, r2 = 0.f, r3 = 0.f;
        #pragma unroll 4
        for (int j = 0; j < HH; j += 4) {
            r0 = fmaf(s_v[j + 0], g_VZ[(j + 0) * HH + h], r0);
            r1 = fmaf(s_v[j + 1], g_VZ[(j + 1) * HH + h], r1);
            r2 = fmaf(s_v[j + 2], g_VZ[(j + 2) * HH + h], r2);
            r3 = fmaf(s_v[j + 3], g_VZ[(j + 3) * HH + h], r3);
        }
        rec = (r0 + r1) + (r2 + r3);
    }

    const float* wxp = g_Wx + (size_t)b * TT * HH + h;
    float*       op  = out  + (size_t)b * TT * HH + h;

    for (int t = 0; t < TT; t++) {
        const float wx = __ldcs(wxp + (size_t)t * HH);
        ut = a * (ut - st_prev) + oma * (wx + rec);
        const float st_new = (ut > 1.0f) ? 1.0f : 0.0f;
        __stcs(op + (size_t)t * HH, st_new);

        // Build the firing list for the next step's gather.
        const unsigned m = __ballot_sync(0xffffffffu, st_new != 0.0f);
        if (lane == 0) s_wcnt[wid] = __popc(m);
        __syncthreads();
        if (h < 32) {
            int v = (h < 16) ? s_wcnt[h] : 0;
            #pragma unroll
            for (int off = 1; off < 16; off <<= 1) {
                int u = __shfl_up_sync(0xffffffffu, v, off);
                if (lane >= off) v += u;
            }
            if (h < 16) s_woff[h] = v - s_wcnt[h];
            if (h == 15) s_total = v;
        }
        __syncthreads();
        if (st_new != 0.0f) {
            const int pos = s_woff[wid] + __popc(m & ((1u << lane) - 1u));
            s_list[pos] = h;
        }
        __syncthreads();

        // Sparse gather: rec[h] = sum over firing j of VZ[j][h]
        const int n = s_total;
        float r0 = 0.f, r1 = 0.f, r2 = 0.f, r3 = 0.f;
        int j = 0;
        for (; j + 4 <= n; j += 4) {
            const int i0 = s_list[j], i1 = s_list[j + 1];
            const int i2 = s_list[j + 2], i3 = s_list[j + 3];
            r0 += g_VZ[i0 * HH + h];
            r1 += g_VZ[i1 * HH + h];
            r2 += g_VZ[i2 * HH + h];
            r3 += g_VZ[i3 * HH + h];
        }
        for (; j < n; j++) r0 += g_VZ[s_list[j] * HH + h];
        rec = (r0 + r1) + (r2 + r3);

        st_prev = st_new;
    }
}

// ---------------------------------------------------------------------------
// Launch: inputs per metadata order: x, W, V, alpha, ut0, st0, input_layer
// ---------------------------------------------------------------------------
extern "C" void kernel_launch(void* const* d_in, const int* in_sizes, int n_in,
                              void* d_out, int out_size) {
    const float* x     = (const float*)d_in[0];
    const float* W     = (const float*)d_in[1];
    const float* V     = (const float*)d_in[2];
    const float* alpha = (const float*)d_in[3];
    const float* ut0   = (const float*)d_in[4];
    const float* st0   = (const float*)d_in[5];
    float* out = (float*)d_out;

    make_vz_kernel<<<(HH * HH + 511) / 512, 512>>>(V);

    dim3 ggrid(MM / BMT, HH / BNT);   // 500 x 4
    sgemm_nt_kernel<<<ggrid, 256>>>(x, W);

    scan_kernel<<<BB, HH>>>(alpha, ut0, st0, out);
}

// round 3
// speedup vs baseline: 1.4579x; 1.4579x over previous
#include <cuda_runtime.h>
#include <cstdint>

// Problem dims (fixed by the dataset)
#define BB   64
#define TT   1000
#define INN  512
#define HH   512
#define MM   (BB * TT)   // 64000

// Scratch
__device__ float g_Wx[MM * HH];        // 131 MB  GEMM output
__device__ float g_VZ[HH * HH];        // 1 MB    V with zero diagonal

__device__ __forceinline__ float tf32_rn(float x) {
    uint32_t b;
    asm("cvt.rna.tf32.f32 %0, %1;" : "=r"(b) : "f"(x));
    return __uint_as_float(b);
}

// ---------------------------------------------------------------------------
// Kernel 0: VZ = V with zero diagonal
// ---------------------------------------------------------------------------
__global__ void make_vz_kernel(const float* __restrict__ V) {
    int i = blockIdx.x * blockDim.x + threadIdx.x;
    if (i < HH * HH) {
        int r = i >> 9;
        int c = i & (HH - 1);
        g_VZ[i] = (r == c) ? 0.0f : V[i];
    }
}

// ---------------------------------------------------------------------------
// Kernel 1: 3xTF32 GEMM via mma.sync m16n8k8 (legacy tensor pipe, sm_80+ PTX)
//   Wx[m,n] = sum_k x[m,k] * W[n,k]
//   Tile 128x128x16, 256 threads, warp tile 64x32. hi/lo tf32 split done on
//   the smem store; per k-step: acc += Ah*Bh + Ah*Bl + Al*Bh.
// ---------------------------------------------------------------------------
#define GBM 128
#define GBN 128
#define GBK 16
#define LDP (GBK + 4)     // smem row stride (floats): conflict-free frags
#define NCHNK (INN / GBK) // 32

#define MMA_TF32(d, a, b)                                                     \
    asm volatile(                                                             \
        "mma.sync.aligned.m16n8k8.row.col.f32.tf32.tf32.f32 "                 \
        "{%0,%1,%2,%3},{%4,%5,%6,%7},{%8,%9},{%0,%1,%2,%3};"                  \
        : "+f"((d)[0]), "+f"((d)[1]), "+f"((d)[2]), "+f"((d)[3])              \
        : "r"((a)[0]), "r"((a)[1]), "r"((a)[2]), "r"((a)[3]),                 \
          "r"((b)[0]), "r"((b)[1]))

__global__ void __launch_bounds__(256, 1) gemm3tf32_kernel(
    const float* __restrict__ X, const float* __restrict__ W)
{
    __shared__ float As_hi[GBM][LDP];
    __shared__ float As_lo[GBM][LDP];
    __shared__ float Bs_hi[GBN][LDP];
    __shared__ float Bs_lo[GBN][LDP];

    const int tid  = threadIdx.x;
    const int lane = tid & 31;
    const int wm   = (tid >> 5) & 1;   // warp m: 0..1 (64 rows each)
    const int wn   = (tid >> 6);       // warp n: 0..3 (32 cols each)
    const int g    = lane >> 2;        // group 0..7
    const int tg   = lane & 3;         // thread-in-group 0..3

    const int    n0 = blockIdx.x * GBN;         // n tiles fastest -> X L2 reuse
    const size_t m0 = (size_t)blockIdx.y * GBM;

    // global-load mapping: each thread owns one row-chunk of 8 floats
    const int grow = tid >> 1;          // 0..127
    const int gcol = (tid & 1) * 8;     // 0 or 8
    const float* Xp = X + (m0 + grow) * INN + gcol;
    const float* Wp = W + (size_t)(n0 + grow) * INN + gcol;

    float4 xa0 = *(const float4*)(Xp);
    float4 xa1 = *(const float4*)(Xp + 4);
    float4 wb0 = *(const float4*)(Wp);
    float4 wb1 = *(const float4*)(Wp + 4);

    float acc[4][4][4];
    #pragma unroll
    for (int i = 0; i < 4; i++)
        #pragma unroll
        for (int j = 0; j < 4; j++)
            #pragma unroll
            for (int q = 0; q < 4; q++) acc[i][j][q] = 0.0f;

    for (int c = 0; c < NCHNK; c++) {
        __syncthreads();
        // split + store this chunk
        {
            float v[8] = {xa0.x, xa0.y, xa0.z, xa0.w, xa1.x, xa1.y, xa1.z, xa1.w};
            #pragma unroll
            for (int i = 0; i < 8; i++) {
                float hi = tf32_rn(v[i]);
                As_hi[grow][gcol + i] = hi;
                As_lo[grow][gcol + i] = tf32_rn(v[i] - hi);
            }
            float w[8] = {wb0.x, wb0.y, wb0.z, wb0.w, wb1.x, wb1.y, wb1.z, wb1.w};
            #pragma unroll
            for (int i = 0; i < 8; i++) {
                float hi = tf32_rn(w[i]);
                Bs_hi[grow][gcol + i] = hi;
                Bs_lo[grow][gcol + i] = tf32_rn(w[i] - hi);
            }
        }
        __syncthreads();

        if (c + 1 < NCHNK) {
            const int k0 = (c + 1) * GBK;
            xa0 = *(const float4*)(Xp + k0);
            xa1 = *(const float4*)(Xp + k0 + 4);
            wb0 = *(const float4*)(Wp + k0);
            wb1 = *(const float4*)(Wp + k0 + 4);
        }

        #pragma unroll
        for (int ks = 0; ks < 2; ks++) {
            const int k0 = ks * 8;
            uint32_t ah[4][4], al[4][4], bh[4][2], bl[4][2];
            #pragma unroll
            for (int mb = 0; mb < 4; mb++) {
                const int r = wm * 64 + mb * 16 + g;
                ah[mb][0] = __float_as_uint(As_hi[r][k0 + tg]);
                ah[mb][1] = __float_as_uint(As_hi[r + 8][k0 + tg]);
                ah[mb][2] = __float_as_uint(As_hi[r][k0 + tg + 4]);
                ah[mb][3] = __float_as_uint(As_hi[r + 8][k0 + tg + 4]);
                al[mb][0] = __float_as_uint(As_lo[r][k0 + tg]);
                al[mb][1] = __float_as_uint(As_lo[r + 8][k0 + tg]);
                al[mb][2] = __float_as_uint(As_lo[r][k0 + tg + 4]);
                al[mb][3] = __float_as_uint(As_lo[r + 8][k0 + tg + 4]);
            }
            #pragma unroll
            for (int nb = 0; nb < 4; nb++) {
                const int n = wn * 32 + nb * 8 + g;
                bh[nb][0] = __float_as_uint(Bs_hi[n][k0 + tg]);
                bh[nb][1] = __float_as_uint(Bs_hi[n][k0 + tg + 4]);
                bl[nb][0] = __float_as_uint(Bs_lo[n][k0 + tg]);
                bl[nb][1] = __float_as_uint(Bs_lo[n][k0 + tg + 4]);
            }
            #pragma unroll
            for (int mb = 0; mb < 4; mb++)
                #pragma unroll
                for (int nb = 0; nb < 4; nb++) {
                    MMA_TF32(acc[mb][nb], ah[mb], bh[nb]);
                    MMA_TF32(acc[mb][nb], ah[mb], bl[nb]);
                    MMA_TF32(acc[mb][nb], al[mb], bh[nb]);
                }
        }
    }

    // epilogue: c0,c1 -> (row, col0..1); c2,c3 -> (row+8, col0..1)
    #pragma unroll
    for (int mb = 0; mb < 4; mb++) {
        const size_t r = m0 + wm * 64 + mb * 16 + g;
        #pragma unroll
        for (int nb = 0; nb < 4; nb++) {
            const int col = n0 + wn * 32 + nb * 8 + tg * 2;
            *(float2*)(g_Wx + r * HH + col) =
                make_float2(acc[mb][nb][0], acc[mb][nb][1]);
            *(float2*)(g_Wx + (r + 8) * HH + col) =
                make_float2(acc[mb][nb][2], acc[mb][nb][3]);
        }
    }
}

// ---------------------------------------------------------------------------
// Kernel 2: recurrent scan. One CTA per batch, thread h owns neuron h.
//   8-deep register prefetch of wx hides memory latency; __syncthreads_count
//   fast-path skips list building when no neuron fires.
// ---------------------------------------------------------------------------
__global__ void __launch_bounds__(512, 1) scan_kernel(
    const float* __restrict__ alpha,
    const float* __restrict__ ut0,
    const float* __restrict__ st0,
    float* __restrict__ out)
{
    const int b    = blockIdx.x;
    const int h    = threadIdx.x;
    const int lane = h & 31;
    const int wid  = h >> 5;

    __shared__ float s_v[HH];
    __shared__ int   s_list[HH];
    __shared__ int   s_wcnt[16];
    __shared__ int   s_woff[16];
    __shared__ int   s_total;

    const float a   = fminf(fmaxf(alpha[h], 0.81873075307798182f), 0.96078943915232320f);
    const float oma = 1.0f - a;

    float ut      = ut0[b * HH + h];
    float st_prev = st0[b * HH + h];

    s_v[h] = st_prev;
    __syncthreads();

    // Dense recurrent input for step 0 (continuous st0)
    float rec;
    {
        float r0 = 0.f, r1 = 0.f, r2 = 0.f, r3 = 0.f;
        #pragma unroll 4
        for (int j = 0; j < HH; j += 4) {
            r0 = fmaf(s_v[j + 0], g_VZ[(j + 0) * HH + h], r0);
            r1 = fmaf(s_v[j + 1], g_VZ[(j + 1) * HH + h], r1);
            r2 = fmaf(s_v[j + 2], g_VZ[(j + 2) * HH + h], r2);
            r3 = fmaf(s_v[j + 3], g_VZ[(j + 3) * HH + h], r3);
        }
        rec = (r0 + r1) + (r2 + r3);
    }

    const float* wxp = g_Wx + (size_t)b * TT * HH + h;
    float*       op  = out  + (size_t)b * TT * HH + h;

    float wxb[8];
    #pragma unroll
    for (int i = 0; i < 8; i++) wxb[i] = __ldcs(wxp + (size_t)i * HH);

    for (int t0 = 0; t0 < TT; t0 += 8) {
        #pragma unroll
        for (int u = 0; u < 8; u++) {
            const int t = t0 + u;
            const float wx = wxb[u];
            if (t + 8 < TT) wxb[u] = __ldcs(wxp + (size_t)(t + 8) * HH);

            ut = a * (ut - st_prev) + oma * (wx + rec);
            const float st_new = (ut > 1.0f) ? 1.0f : 0.0f;
            __stcs(op + (size_t)t * HH, st_new);

            const int nf = __syncthreads_count(st_new != 0.0f);
            if (nf == 0) { rec = 0.0f; st_prev = st_new; continue; }

            // Build firing list
            const unsigned m = __ballot_sync(0xffffffffu, st_new != 0.0f);
            if (lane == 0) s_wcnt[wid] = __popc(m);
            __syncthreads();
            if (h < 32) {
                int v = (h < 16) ? s_wcnt[h] : 0;
                #pragma unroll
                for (int off = 1; off < 16; off <<= 1) {
                    int uu = __shfl_up_sync(0xffffffffu, v, off);
                    if (lane >= off) v += uu;
                }
                if (h < 16) s_woff[h] = v - s_wcnt[h];
                if (h == 15) s_total = v;
            }
            __syncthreads();
            if (st_new != 0.0f) {
                const int pos = s_woff[wid] + __popc(m & ((1u << lane) - 1u));
                s_list[pos] = h;
            }
            __syncthreads();

            const int n = s_total;
            float r0 = 0.f, r1 = 0.f, r2 = 0.f, r3 = 0.f;
            int j = 0;
            for (; j + 4 <= n; j += 4) {
                const int i0 = s_list[j],     i1 = s_list[j + 1];
                const int i2 = s_list[j + 2], i3 = s_list[j + 3];
                r0 += g_VZ[i0 * HH + h];
                r1 += g_VZ[i1 * HH + h];
                r2 += g_VZ[i2 * HH + h];
                r3 += g_VZ[i3 * HH + h];
            }
            for (; j < n; j++) r0 += g_VZ[s_list[j] * HH + h];
            rec = (r0 + r1) + (r2 + r3);

            st_prev = st_new;
        }
    }
}

// ---------------------------------------------------------------------------
// Launch: inputs: x, W, V, alpha, ut0, st0, input_layer
// ---------------------------------------------------------------------------
extern "C" void kernel_launch(void* const* d_in, const int* in_sizes, int n_in,
                              void* d_out, int out_size) {
    const float* x     = (const float*)d_in[0];
    const float* W     = (const float*)d_in[1];
    const float* V     = (const float*)d_in[2];
    const float* alpha = (const float*)d_in[3];
    const float* ut0   = (const float*)d_in[4];
    const float* st0   = (const float*)d_in[5];
    float* out = (float*)d_out;

    make_vz_kernel<<<(HH * HH + 511) / 512, 512>>>(V);

    dim3 ggrid(HH / GBN, MM / GBM);   // 4 x 500 (n-tiles fastest)
    gemm3tf32_kernel<<<ggrid, 256>>>(x, W);

    scan_kernel<<<BB, HH>>>(alpha, ut0, st0, out);
}

// round 4
// speedup vs baseline: 1.7785x; 1.2199x over previous
#include <cuda_runtime.h>
#include <cstdint>

// Problem dims (fixed by the dataset)
#define BB   64
#define TT   1000
#define INN  512
#define HH   512
#define MM   (BB * TT)   // 64000

// Scratch
__device__ float g_Wx[MM * HH];        // 131 MB  GEMM output

__device__ __forceinline__ float tf32_rn(float x) {
    uint32_t b;
    asm("cvt.rna.tf32.f32 %0, %1;" : "=r"(b) : "f"(x));
    return __uint_as_float(b);
}

// ---------------------------------------------------------------------------
// Kernel 1: 3xTF32 GEMM via mma.sync m16n8k8.  Wx[m,n] = sum_k x[m,k] W[n,k]
//   Tile 128x128x32, 256 threads, warp tile 64x32. Double-buffered dynamic
//   smem (2 x 72KB): stores/loads for chunk c+1/c+2 overlap the MMA stream of
//   chunk c; ONE barrier per chunk. hi/lo tf32 split on the smem store.
// ---------------------------------------------------------------------------
#define GBM 128
#define GBN 128
#define GBK 32
#define LDP 36                       // (4g+tg) mod 32 -> conflict-free frags
#define NCHNK (INN / GBK)            // 16
#define TILE_F (GBM * LDP)           // 4608 floats per array
#define STAGE_F (4 * TILE_F)         // As_hi|As_lo|Bs_hi|Bs_lo
#define GEMM_SMEM (2 * STAGE_F * 4)  // 147456 bytes

#define MMA_TF32(d, a, b)                                                     \
    asm volatile(                                                             \
        "mma.sync.aligned.m16n8k8.row.col.f32.tf32.tf32.f32 "                 \
        "{%0,%1,%2,%3},{%4,%5,%6,%7},{%8,%9},{%0,%1,%2,%3};"                  \
        : "+f"((d)[0]), "+f"((d)[1]), "+f"((d)[2]), "+f"((d)[3])              \
        : "r"((a)[0]), "r"((a)[1]), "r"((a)[2]), "r"((a)[3]),                 \
          "r"((b)[0]), "r"((b)[1]))

__global__ void __launch_bounds__(256, 1) gemm3tf32_kernel(
    const float* __restrict__ X, const float* __restrict__ W)
{
    extern __shared__ __align__(16) float sm[];

    const int tid  = threadIdx.x;
    const int lane = tid & 31;
    const int wm   = (tid >> 5) & 1;   // warp m: 0..1 (64 rows each)
    const int wn   = (tid >> 6);       // warp n: 0..3 (32 cols each)
    const int g    = lane >> 2;        // group 0..7
    const int tg   = lane & 3;         // thread-in-group 0..3

    const int    n0 = blockIdx.x * GBN;          // n-tiles fastest -> X L2 reuse
    const size_t m0 = (size_t)blockIdx.y * GBM;

    // global-load mapping: thread owns 16 consecutive floats of one row
    const int grow = tid >> 1;          // 0..127
    const int gh   = (tid & 1) * 16;    // 0 or 16
    const float* Xp = X + (m0 + grow) * INN + gh;
    const float* Wp = W + (size_t)(n0 + grow) * INN + gh;

    float4 xa[4], wb[4];

    float acc[4][4][4];
    #pragma unroll
    for (int i = 0; i < 4; i++)
        #pragma unroll
        for (int j = 0; j < 4; j++)
            #pragma unroll
            for (int q = 0; q < 4; q++) acc[i][j][q] = 0.0f;

    auto gload = [&](int c) {
        const int k0 = c * GBK;
        #pragma unroll
        for (int q = 0; q < 4; q++) {
            xa[q] = *(const float4*)(Xp + k0 + 4 * q);
            wb[q] = *(const float4*)(Wp + k0 + 4 * q);
        }
    };
    auto sstore = [&](int s) {
        float* As_hi = sm + s * STAGE_F;
        float* As_lo = As_hi + TILE_F;
        float* Bs_hi = As_lo + TILE_F;
        float* Bs_lo = Bs_hi + TILE_F;
        const int idx = grow * LDP + gh;
        #pragma unroll
        for (int q = 0; q < 4; q++) {
            float4 v = xa[q], hi, lo;
            hi.x = tf32_rn(v.x); lo.x = tf32_rn(v.x - hi.x);
            hi.y = tf32_rn(v.y); lo.y = tf32_rn(v.y - hi.y);
            hi.z = tf32_rn(v.z); lo.z = tf32_rn(v.z - hi.z);
            hi.w = tf32_rn(v.w); lo.w = tf32_rn(v.w - hi.w);
            *(float4*)(As_hi + idx + 4 * q) = hi;
            *(float4*)(As_lo + idx + 4 * q) = lo;
            float4 w = wb[q], whi, wlo;
            whi.x = tf32_rn(w.x); wlo.x = tf32_rn(w.x - whi.x);
            whi.y = tf32_rn(w.y); wlo.y = tf32_rn(w.y - whi.y);
            whi.z = tf32_rn(w.z); wlo.z = tf32_rn(w.z - whi.z);
            whi.w = tf32_rn(w.w); wlo.w = tf32_rn(w.w - whi.w);
            *(float4*)(Bs_hi + idx + 4 * q) = whi;
            *(float4*)(Bs_lo + idx + 4 * q) = wlo;
        }
    };

    gload(0);
    sstore(0);
    gload(1);
    __syncthreads();

    for (int c = 0; c < NCHNK; c++) {
        const int cur = c & 1;
        if (c + 1 < NCHNK) sstore(1 - cur);   // overlaps MMA below
        if (c + 2 < NCHNK) gload(c + 2);      // overlaps MMA below

        const float* As_hi = sm + cur * STAGE_F;
        const float* As_lo = As_hi + TILE_F;
        const float* Bs_hi = As_lo + TILE_F;
        const float* Bs_lo = Bs_hi + TILE_F;

        #pragma unroll
        for (int ks = 0; ks < 4; ks++) {
            const int k0 = ks * 8;
            uint32_t ah[4][4], al[4][4], bh[4][2], bl[4][2];
            #pragma unroll
            for (int mb = 0; mb < 4; mb++) {
                const int r = (wm * 64 + mb * 16 + g) * LDP + k0 + tg;
                ah[mb][0] = __float_as_uint(As_hi[r]);
                ah[mb][1] = __float_as_uint(As_hi[r + 8 * LDP]);
                ah[mb][2] = __float_as_uint(As_hi[r + 4]);
                ah[mb][3] = __float_as_uint(As_hi[r + 8 * LDP + 4]);
                al[mb][0] = __float_as_uint(As_lo[r]);
                al[mb][1] = __float_as_uint(As_lo[r + 8 * LDP]);
                al[mb][2] = __float_as_uint(As_lo[r + 4]);
                al[mb][3] = __float_as_uint(As_lo[r + 8 * LDP + 4]);
            }
            #pragma unroll
            for (int nb = 0; nb < 4; nb++) {
                const int n = (wn * 32 + nb * 8 + g) * LDP + k0 + tg;
                bh[nb][0] = __float_as_uint(Bs_hi[n]);
                bh[nb][1] = __float_as_uint(Bs_hi[n + 4]);
                bl[nb][0] = __float_as_uint(Bs_lo[n]);
                bl[nb][1] = __float_as_uint(Bs_lo[n + 4]);
            }
            #pragma unroll
            for (int mb = 0; mb < 4; mb++)
                #pragma unroll
                for (int nb = 0; nb < 4; nb++) {
                    MMA_TF32(acc[mb][nb], ah[mb], bh[nb]);
                    MMA_TF32(acc[mb][nb], ah[mb], bl[nb]);
                    MMA_TF32(acc[mb][nb], al[mb], bh[nb]);
                }
        }
        __syncthreads();
    }

    // epilogue
    #pragma unroll
    for (int mb = 0; mb < 4; mb++) {
        const size_t r = m0 + wm * 64 + mb * 16 + g;
        #pragma unroll
        for (int nb = 0; nb < 4; nb++) {
            const int col = n0 + wn * 32 + nb * 8 + tg * 2;
            *(float2*)(g_Wx + r * HH + col) =
                make_float2(acc[mb][nb][0], acc[mb][nb][1]);
            *(float2*)(g_Wx + (r + 8) * HH + col) =
                make_float2(acc[mb][nb][2], acc[mb][nb][3]);
        }
    }
}

// ---------------------------------------------------------------------------
// Kernel 2: recurrent scan. One CTA per batch, thread h owns neuron h.
//   2 barriers per firing step (1 when silent). Warp ballot masks published
//   before __syncthreads_count (which doubles as the publication barrier and
//   returns nf). Gather reads V directly with MLP=8; diagonal term removed by
//   subtracting V[h][h] when self fired.
// ---------------------------------------------------------------------------
__global__ void __launch_bounds__(512, 1) scan_kernel(
    const float* __restrict__ alpha,
    const float* __restrict__ ut0,
    const float* __restrict__ st0,
    const float* __restrict__ V,
    float* __restrict__ out)
{
    const int b    = blockIdx.x;
    const int h    = threadIdx.x;
    const int lane = h & 31;
    const int wid  = h >> 5;

    __shared__ float    s_v[HH];
    __shared__ int      s_list[HH];
    __shared__ unsigned s_mask[16];

    const float a   = fminf(fmaxf(alpha[h], 0.81873075307798182f), 0.96078943915232320f);
    const float oma = 1.0f - a;
    const float vdiag = V[h * HH + h];

    float ut      = ut0[b * HH + h];
    float st_prev = st0[b * HH + h];

    s_v[h] = st_prev;
    __syncthreads();

    // Dense recurrent input for step 0 (continuous st0); remove diagonal term.
    float rec;
    {
        float r0 = 0.f, r1 = 0.f, r2 = 0.f, r3 = 0.f;
        #pragma unroll 4
        for (int j = 0; j < HH; j += 4) {
            r0 = fmaf(s_v[j + 0], V[(j + 0) * HH + h], r0);
            r1 = fmaf(s_v[j + 1], V[(j + 1) * HH + h], r1);
            r2 = fmaf(s_v[j + 2], V[(j + 2) * HH + h], r2);
            r3 = fmaf(s_v[j + 3], V[(j + 3) * HH + h], r3);
        }
        rec = ((r0 + r1) + (r2 + r3)) - st_prev * vdiag;
    }

    const float* wxp = g_Wx + (size_t)b * TT * HH + h;
    float*       op  = out  + (size_t)b * TT * HH + h;

    float wxb[8];
    #pragma unroll
    for (int i = 0; i < 8; i++) wxb[i] = __ldcs(wxp + (size_t)i * HH);

    for (int t0 = 0; t0 < TT; t0 += 8) {
        #pragma unroll
        for (int u = 0; u < 8; u++) {
            const int t = t0 + u;
            const float wx = wxb[u];
            if (t + 8 < TT) wxb[u] = __ldcs(wxp + (size_t)(t + 8) * HH);

            ut = a * (ut - st_prev) + oma * (wx + rec);
            const float st_new = (ut > 1.0f) ? 1.0f : 0.0f;
            __stcs(op + (size_t)t * HH, st_new);

            const bool fired = (st_new != 0.0f);
            const unsigned m = __ballot_sync(0xffffffffu, fired);
            if (lane == 0) s_mask[wid] = m;

            const int nf = __syncthreads_count(fired);   // barrier A (publishes s_mask)
            if (nf == 0) { rec = 0.0f; st_prev = st_new; continue; }

            int off = 0;
            #pragma unroll
            for (int w = 0; w < 16; w++)
                off += (w < wid) ? __popc(s_mask[w]) : 0;
            if (fired)
                s_list[off + __popc(m & ((1u << lane) - 1u))] = h;
            __syncthreads();                              // barrier B (list visible)

            float rr0 = 0.f, rr1 = 0.f, rr2 = 0.f, rr3 = 0.f;
            float rr4 = 0.f, rr5 = 0.f, rr6 = 0.f, rr7 = 0.f;
            int j = 0;
            for (; j + 8 <= nf; j += 8) {
                const int i0 = s_list[j + 0], i1 = s_list[j + 1];
                const int i2 = s_list[j + 2], i3 = s_list[j + 3];
                const int i4 = s_list[j + 4], i5 = s_list[j + 5];
                const int i6 = s_list[j + 6], i7 = s_list[j + 7];
                rr0 += __ldg(V + i0 * HH + h);
                rr1 += __ldg(V + i1 * HH + h);
                rr2 += __ldg(V + i2 * HH + h);
                rr3 += __ldg(V + i3 * HH + h);
                rr4 += __ldg(V + i4 * HH + h);
                rr5 += __ldg(V + i5 * HH + h);
                rr6 += __ldg(V + i6 * HH + h);
                rr7 += __ldg(V + i7 * HH + h);
            }
            for (; j < nf; j++) rr0 += __ldg(V + s_list[j] * HH + h);

            rec = (((rr0 + rr1) + (rr2 + rr3)) + ((rr4 + rr5) + (rr6 + rr7)))
                  - (fired ? vdiag : 0.0f);

            st_prev = st_new;
        }
    }
}

// ---------------------------------------------------------------------------
// Launch: inputs: x, W, V, alpha, ut0, st0, input_layer
// ---------------------------------------------------------------------------
extern "C" void kernel_launch(void* const* d_in, const int* in_sizes, int n_in,
                              void* d_out, int out_size) {
    const float* x     = (const float*)d_in[0];
    const float* W     = (const float*)d_in[1];
    const float* V     = (const float*)d_in[2];
    const float* alpha = (const float*)d_in[3];
    const float* ut0   = (const float*)d_in[4];
    const float* st0   = (const float*)d_in[5];
    float* out = (float*)d_out;

    cudaFuncSetAttribute(gemm3tf32_kernel,
                         cudaFuncAttributeMaxDynamicSharedMemorySize, GEMM_SMEM);

    dim3 ggrid(HH / GBN, MM / GBM);   // 4 x 500 (n-tiles fastest)
    gemm3tf32_kernel<<<ggrid, 256, GEMM_SMEM>>>(x, W);

    scan_kernel<<<BB, HH>>>(alpha, ut0, st0, V, out);
}